// round 2
// baseline (speedup 1.0000x reference)
#include <cuda_runtime.h>
#include <cuda_bf16.h>

typedef unsigned long long u64;

#define T_LEN 128
#define H3    60
#define HID   20
#define LOUT  15
#define NBATCH 2048

__device__ __forceinline__ u64 fma2(u64 a, u64 b, u64 c){
  u64 d; asm("fma.rn.f32x2 %0, %1, %2, %3;" : "=l"(d) : "l"(a), "l"(b), "l"(c)); return d;
}
__device__ __forceinline__ u64 add2(u64 a, u64 b){
  u64 d; asm("add.rn.f32x2 %0, %1, %2;" : "=l"(d) : "l"(a), "l"(b)); return d;
}
__device__ __forceinline__ u64 pack2(float x, float y){
  u64 d; asm("mov.b64 %0, {%1, %2};" : "=l"(d) : "f"(x), "f"(y)); return d;
}
__device__ __forceinline__ float sigf(float x){
  return __fdividef(1.f, 1.f + __expf(-x));
}
__device__ __forceinline__ float tanh_fast(float x){
  // tanh(x) = 2*sigmoid(2x) - 1 ; correct limits at +/- inf
  return __fdividef(2.f, 1.f + __expf(-2.f * x)) - 1.f;
}

__global__ void __launch_bounds__(32) gru2_kernel(
    const int*   __restrict__ x,
    const float* __restrict__ W0,
    const float* __restrict__ U0,  const float* __restrict__ b0i, const float* __restrict__ b0r,
    const float* __restrict__ W1,  const float* __restrict__ U1,
    const float* __restrict__ b1i, const float* __restrict__ b1r,
    const float* __restrict__ Wd,  const float* __restrict__ bd,
    float* __restrict__ out)
{
  const int t     = threadIdx.x;
  const int bbase = blockIdx.x * 2;
  const int jc    = (t < 30) ? 2 * t : 0;   // column pair owned by this lane

  // hidden states stored DUPLICATED: hd[be][2k]=hd[be][2k+1]=h_k -> one LDS.64 = {h,h} f32x2 operand
  __shared__ __align__(16) float hd0[2][40];
  __shared__ __align__(16) float hd1[2][40];
  __shared__ __align__(8)  float sA[2][64];   // cols 0..39: xw+rec combined; cols 40..59: xw part
  __shared__ __align__(8)  float sR[2][64];   // cols 40..59: rec part
  __shared__ int xs[2][T_LEN];

  // ---- resident weights: packed f32x2 column pairs ----
  u64 u0w[HID], w1w[HID], u1w[HID];
#pragma unroll
  for (int k = 0; k < HID; k++){
    u0w[k] = *(const u64*)(U0 + k * H3 + jc);
    w1w[k] = *(const u64*)(W1 + k * H3 + jc);
    u1w[k] = *(const u64*)(U1 + k * H3 + jc);
  }
  const u64 b0ip = *(const u64*)(b0i + jc);
  const u64 b0rp = *(const u64*)(b0r + jc);
  const u64 b1ip = *(const u64*)(b1i + jc);
  const u64 b1rp = *(const u64*)(b1r + jc);

#pragma unroll
  for (int i = t; i < 40; i += 32){
    hd0[0][i] = 0.f; hd0[1][i] = 0.f;
    hd1[0][i] = 0.f; hd1[1][i] = 0.f;
  }
#pragma unroll 4
  for (int i = t; i < T_LEN; i += 32){
    xs[0][i] = x[(long)bbase * T_LEN + i];
    xs[1][i] = x[(long)(bbase + 1) * T_LEN + i];
  }
  __syncwarp();

  float hp0[2] = {0.f, 0.f};   // lane t<20 keeps h_t of layer0/1 per batch element
  float hp1[2] = {0.f, 0.f};

  u64 gx[2];
  gx[0] = *(const u64*)(W0 + xs[0][0] * H3 + jc);
  gx[1] = *(const u64*)(W0 + xs[1][0] * H3 + jc);

  for (int step = 0; step < T_LEN; step++){
    // prefetch next step's W0 gather (hides L1/L2 latency behind this step's work)
    const int nt = (step + 1 < T_LEN) ? step + 1 : step;
    const u64 ngx0 = *(const u64*)(W0 + xs[0][nt] * H3 + jc);
    const u64 ngx1 = *(const u64*)(W0 + xs[1][nt] * H3 + jc);

    // ================= layer 0: rec = h0 @ U0 + b0r ; combine with xw =================
#pragma unroll
    for (int be = 0; be < 2; be++){
      u64 acc = add2(gx[be], b0ip);
      u64 ra = b0rp, rb = 0ull;          // two chains to halve FFMA2 dependency depth
#pragma unroll
      for (int k = 0; k < HID; k += 2){
        ra = fma2(u0w[k],   *(const u64*)&hd0[be][2*k],     ra);
        rb = fma2(u0w[k+1], *(const u64*)&hd0[be][2*k + 2], rb);
      }
      const u64 rec = add2(ra, rb);
      if (t < 20){
        *(u64*)&sA[be][jc] = add2(acc, rec);   // z,r regions combine directly
      } else if (t < 30){
        *(u64*)&sA[be][jc] = acc;              // xh
        *(u64*)&sR[be][jc] = rec;              // rh (needs r * rh)
      }
    }
    __syncwarp();

    if (t < HID){
#pragma unroll
      for (int be = 0; be < 2; be++){
        const float z  = sigf(sA[be][t]);
        const float r  = sigf(sA[be][20 + t]);
        const float hh = tanh_fast(sA[be][40 + t] + r * sR[be][40 + t]);
        const float hn = z * hp0[be] + (1.f - z) * hh;
        hp0[be] = hn;
        *(u64*)&hd0[be][2*t] = pack2(hn, hn);
      }
    }
    __syncwarp();

    // ============ layer 1: xw1 = h0 @ W1 + b1i ; rec1 = h1 @ U1 + b1r ============
#pragma unroll
    for (int be = 0; be < 2; be++){
      u64 aa = b1ip, ab = 0ull;
      u64 ra = b1rp, rb = 0ull;
#pragma unroll
      for (int k = 0; k < HID; k += 2){
        aa = fma2(w1w[k],   *(const u64*)&hd0[be][2*k],     aa);
        ab = fma2(w1w[k+1], *(const u64*)&hd0[be][2*k + 2], ab);
        ra = fma2(u1w[k],   *(const u64*)&hd1[be][2*k],     ra);
        rb = fma2(u1w[k+1], *(const u64*)&hd1[be][2*k + 2], rb);
      }
      const u64 acc = add2(aa, ab);
      const u64 rec = add2(ra, rb);
      if (t < 20){
        *(u64*)&sA[be][jc] = add2(acc, rec);
      } else if (t < 30){
        *(u64*)&sA[be][jc] = acc;
        *(u64*)&sR[be][jc] = rec;
      }
    }
    __syncwarp();

    if (t < HID){
#pragma unroll
      for (int be = 0; be < 2; be++){
        const float z  = sigf(sA[be][t]);
        const float r  = sigf(sA[be][20 + t]);
        const float hh = tanh_fast(sA[be][40 + t] + r * sR[be][40 + t]);
        const float hn = z * hp1[be] + (1.f - z) * hh;
        hp1[be] = hn;
        *(u64*)&hd1[be][2*t] = pack2(hn, hn);
      }
    }
    __syncwarp();

    gx[0] = ngx0;
    gx[1] = ngx1;
  }

  // ================= epilogue: softmax(h1 @ Wd + bd) =================
#pragma unroll
  for (int be = 0; be < 2; be++){
    float val = -1e30f;
    if (t < LOUT){
      float acc = bd[t];
#pragma unroll
      for (int k = 0; k < HID; k++)
        acc = fmaf(hd1[be][2*k], Wd[k * LOUT + t], acc);
      val = acc;
    }
    float m = val;
#pragma unroll
    for (int off = 16; off > 0; off >>= 1)
      m = fmaxf(m, __shfl_xor_sync(0xffffffffu, m, off));
    const float e = (t < LOUT) ? __expf(val - m) : 0.f;
    float s = e;
#pragma unroll
    for (int off = 16; off > 0; off >>= 1)
      s += __shfl_xor_sync(0xffffffffu, s, off);
    if (t < LOUT)
      out[(long)(bbase + be) * LOUT + t] = __fdividef(e, s);
  }
}

extern "C" void kernel_launch(void* const* d_in, const int* in_sizes, int n_in,
                              void* d_out, int out_size)
{
  const int*   x   = (const int*)  d_in[0];
  const float* W0  = (const float*)d_in[1];
  const float* U0  = (const float*)d_in[2];
  const float* b0i = (const float*)d_in[3];
  const float* b0r = (const float*)d_in[4];
  const float* W1  = (const float*)d_in[5];
  const float* U1  = (const float*)d_in[6];
  const float* b1i = (const float*)d_in[7];
  const float* b1r = (const float*)d_in[8];
  const float* Wd  = (const float*)d_in[9];
  const float* bd  = (const float*)d_in[10];
  // d_in[11] = drop_rate (identity, ignored)
  float* out = (float*)d_out;

  gru2_kernel<<<NBATCH / 2, 32>>>(x, W0, U0, b0i, b0r, W1, U1, b1i, b1r, Wd, bd, out);
}